// round 15
// baseline (speedup 1.0000x reference)
#include <cuda_runtime.h>
#include <cuda_fp16.h>
#include <cstddef>

#define NVV   40962
#define NVP   10242
#define BB    8
#define CC    64
#define KK    7
#define VBLKS 1281              // ceil(40962/32)
#define GN_N  (2*NVV)

#define TM 128                  // v per stage1 block

// Scratch (device globals — zero-initialized; no allocations allowed)
__device__ float  d_Y0[(size_t)BB * NVP * 64];        // up-proj  [b][v][o], 21 MB
__device__ __half d_Yd[(size_t)BB * NVP * 64 * 4];    // {y1,y2,y3,0} [b][v][o][4], 42 MB
__device__ __half d_Sh[(size_t)BB * NVV * 64];        // pre-GN [b][v][o] fp16, 42 MB
__device__ float  d_psum[2 * VBLKS * 128];            // [half][vblk][(b&3)*32+g]
__device__ float  d_psq [2 * VBLKS * 128];
__device__ float  d_mean[256];
__device__ float  d_rstd[256];

#define FMA2(d, a, b, c) \
    asm("fma.rn.f32x2 %0, %1, %2, %3;" : "=l"(d) : "l"(a), "l"(b), "l"(c))

// ---------------------------------------------------------------------------
// Stage 1: y_s[b,v,o] = sum_i coeffs[o,i,s] * x[b,i,v]
// Packed f32x2 FMA, per-launch tile: 128 v x 32 o x 4 s x 4 batches.
// coeffs loaded directly (L1/L2-resident, 64KB).
// ---------------------------------------------------------------------------
__global__ void __launch_bounds__(256) k_stage1(const float* __restrict__ x,
                                                const float* __restrict__ coeffs,
                                                int obase, int bbase)
{
    extern __shared__ float sm[];
    float* As = sm;              // [i][vl] : 64*128
    float* Bs = sm + 64 * TM;    // [i][ol*4+s] : 64*128

    const int b     = bbase + blockIdx.z;
    const int vbase = blockIdx.x * TM;
    const int tid   = threadIdx.x;

    for (int t = tid; t < 64 * 128; t += 256) {
        int i = t >> 7;
        int r = t & 127;
        Bs[t] = coeffs[((obase + (r >> 2)) * 64 + i) * 4 + (r & 3)];
    }
    for (int t = tid; t < 64 * TM; t += 256) {
        int i  = t >> 7;
        int vl = t & 127;
        int v  = vbase + vl;
        As[t]  = (v < NVP) ? x[(b * 64 + i) * NVP + v] : 0.f;
    }
    __syncthreads();

    const int ol0   = (tid & 15) * 2;
    const int v_sub = (tid >> 4) * 8;

    unsigned long long acc[8][4];
#pragma unroll
    for (int a = 0; a < 8; a++)
#pragma unroll
        for (int c = 0; c < 4; c++) acc[a][c] = 0ULL;

#pragma unroll 4
    for (int i = 0; i < 64; i++) {
        const ulonglong2* Ap = (const ulonglong2*)(As + i * TM + v_sub);
        ulonglong2 a01 = Ap[0];
        ulonglong2 a23 = Ap[1];
        unsigned long long av[4] = {a01.x, a01.y, a23.x, a23.y};
        float4 b0 = *(const float4*)(Bs + i * 128 + ol0 * 4);
        float4 b1 = *(const float4*)(Bs + i * 128 + ol0 * 4 + 4);
        float bv[8] = {b0.x, b0.y, b0.z, b0.w, b1.x, b1.y, b1.z, b1.w};
#pragma unroll
        for (int a = 0; a < 8; a++) {
            unsigned bu = __float_as_uint(bv[a]);
            unsigned long long bb;
            asm("mov.b64 %0, {%1, %1};" : "=l"(bb) : "r"(bu));
#pragma unroll
            for (int c = 0; c < 4; c++)
                FMA2(acc[a][c], av[c], bb, acc[a][c]);
        }
    }

#pragma unroll
    for (int c = 0; c < 4; c++) {
#pragma unroll
        for (int par = 0; par < 2; par++) {
            int v = vbase + v_sub + c * 2 + par;
            if (v < NVP) {
                float w[8];
#pragma unroll
                for (int a = 0; a < 8; a++) {
                    unsigned long long u = acc[a][c];
                    w[a] = __uint_as_float(par ? (unsigned)(u >> 32)
                                               : (unsigned)(u & 0xffffffffULL));
                }
                size_t vb = (size_t)b * NVP + v;
                int o0 = obase + ol0;
                *(float2*)(d_Y0 + vb * 64 + o0) = make_float2(w[0], w[4]);
                __half2 p0 = __floats2half2_rn(w[1], w[2]);
                __half2 p1 = __floats2half2_rn(w[3], 0.f);
                __half2 q0 = __floats2half2_rn(w[5], w[6]);
                __half2 q1 = __floats2half2_rn(w[7], 0.f);
                uint4 pk;
                pk.x = *(unsigned*)&p0; pk.y = *(unsigned*)&p1;
                pk.z = *(unsigned*)&q0; pk.w = *(unsigned*)&q1;
                *(uint4*)(d_Yd + (vb * 64 + o0) * 4) = pk;
            }
        }
    }
}

// ---------------------------------------------------------------------------
// Stage 2: gather-combine, 4 batches per block (ty = batch sub-index).
// tx = o-pair; one LDG.128 per hit serves both channels; half2 store to d_Sh.
// ---------------------------------------------------------------------------
__global__ void __launch_bounds__(128) k_stage2(const float* __restrict__ Lw,
                                                const float* __restrict__ Ew,
                                                const float* __restrict__ Nw,
                                                const int*   __restrict__ nbr,
                                                const float* __restrict__ bias)
{
    __shared__ int   s_rj[32 * KK];
    __shared__ float s_rL[32 * KK], s_rE[32 * KK], s_rN[32 * KK];
    __shared__ int4  s_pk[32][KK];          // {j*32, wL, wE, wN}
    __shared__ int   s_cnt[32];

    const int vbase = blockIdx.x * 32;
    const int half  = blockIdx.y;           // batches [half*4, half*4+4)
    const int tx    = threadIdx.x;          // o-pair index (= GN group)
    const int ty    = threadIdx.y;          // batch sub-index
    const int tid   = ty * 32 + tx;
    const int b     = half * 4 + ty;

    for (int t = tid; t < 32 * KK; t += 128) {
        int gidx = vbase * KK + t;
        if (gidx < NVV * KK) {
            s_rj[t] = nbr[gidx];
            s_rL[t] = Lw[gidx]; s_rE[t] = Ew[gidx]; s_rN[t] = Nw[gidx];
        } else {
            s_rj[t] = NVP;
        }
    }
    __syncthreads();
    if (tid < 32) {
        int c = 0;
#pragma unroll
        for (int k = 0; k < KK; k++) {
            int j = s_rj[tid * KK + k];
            if (j < NVP) {
                s_pk[tid][c] = make_int4(j * 32,
                                         __float_as_int(s_rL[tid * KK + k]),
                                         __float_as_int(s_rE[tid * KK + k]),
                                         __float_as_int(s_rN[tid * KK + k]));
                c++;
            }
        }
        s_cnt[tid] = c;
    }
    __syncthreads();

    const float* Y0b  = d_Y0 + (size_t)b * NVP * 64;
    const uint4* Ydb4 = (const uint4*)d_Yd + (size_t)b * NVP * 32;
    __half*      Sb   = d_Sh + (size_t)b * NVV * 64;
    const float2 bo   = *(const float2*)(bias + tx * 2);
    float S = 0.f, Q = 0.f;

    int vmax = NVV - vbase; if (vmax > 32) vmax = 32;   // block-uniform
    for (int vl = 0; vl < vmax; vl++) {
        int v = vbase + vl;
        float acc0 = bo.x, acc1 = bo.y;
        if (v < NVP) {                            // warp-uniform
            float2 y0 = *(const float2*)(Y0b + v * 64 + tx * 2);
            acc0 += y0.x; acc1 += y0.y;
        }
        float aL0 = 0.f, aE0 = 0.f, aN0 = 0.f;
        float aL1 = 0.f, aE1 = 0.f, aN1 = 0.f;
        int cnt = s_cnt[vl];                      // warp-uniform
        for (int kk = 0; kk < cnt; kk++) {
            int4 pk = s_pk[vl][kk];               // LDS.128 (broadcast)
            uint4 q = Ydb4[(size_t)(pk.x + tx)];  // LDG.128: both channels
            float wL = __int_as_float(pk.y);
            float wE = __int_as_float(pk.z);
            float wN = __int_as_float(pk.w);
            float2 f01 = __half22float2(*(__half2*)&q.x);
            float  f3  = __low2float(*(__half2*)&q.y);
            float2 g01 = __half22float2(*(__half2*)&q.z);
            float  g3  = __low2float(*(__half2*)&q.w);
            aL0 = fmaf(wL, f01.x, aL0);
            aE0 = fmaf(wE, f01.y, aE0);
            aN0 = fmaf(wN, f3,    aN0);
            aL1 = fmaf(wL, g01.x, aL1);
            aE1 = fmaf(wE, g01.y, aE1);
            aN1 = fmaf(wN, g3,    aN1);
        }
        acc0 += aL0 + aE0 + aN0;
        acc1 += aL1 + aE1 + aN1;
        S += acc0 + acc1;
        Q = fmaf(acc0, acc0, Q);
        Q = fmaf(acc1, acc1, Q);
        *(__half2*)(Sb + (size_t)v * 64 + tx * 2) = __floats2half2_rn(acc0, acc1);
    }

    // Contiguous partial store: 512B per block
    size_t pidx = ((size_t)half * VBLKS + blockIdx.x) * 128 + tid;
    d_psum[pidx] = S;
    d_psq [pidx] = Q;
}

// ---------------------------------------------------------------------------
// Stage 2.5: reduce partials -> mean / rstd per (b, group). Fixed-order.
// ---------------------------------------------------------------------------
__global__ void __launch_bounds__(256) k_reduce()
{
    __shared__ float sS[256], sQ[256];
    const int bg   = blockIdx.x;
    const int tid  = threadIdx.x;
    const int bb   = bg >> 5;
    const int g    = bg & 31;
    const int half = bb >> 2;
    const int tloc = (bb & 3) * 32 + g;
    const float* P = d_psum + (size_t)half * VBLKS * 128 + tloc;
    const float* R = d_psq  + (size_t)half * VBLKS * 128 + tloc;
    float S = 0.f, Q = 0.f;
    for (int i = tid; i < VBLKS; i += 256) {
        S += P[(size_t)i * 128];
        Q += R[(size_t)i * 128];
    }
    sS[tid] = S; sQ[tid] = Q;
    __syncthreads();
    for (int st = 128; st > 0; st >>= 1) {
        if (tid < st) { sS[tid] += sS[tid + st]; sQ[tid] += sQ[tid + st]; }
        __syncthreads();
    }
    if (tid == 0) {
        float mean = sS[0] * (1.f / (float)GN_N);
        float var  = sQ[0] * (1.f / (float)GN_N) - mean * mean;
        d_mean[bg] = mean;
        d_rstd[bg] = rsqrtf(var + 1e-5f);
    }
}

// ---------------------------------------------------------------------------
// Stage 3: transpose fp16 [b][v][o] -> fp32 [b][o][v] + GN + ReLU.
// ---------------------------------------------------------------------------
__global__ void __launch_bounds__(256) k_stage3(float* __restrict__ out,
                                                const float* __restrict__ gamma,
                                                const float* __restrict__ beta)
{
    __shared__ float s[64][65];

    const int b     = blockIdx.y;
    const int vbase = blockIdx.x * 64;
    const int t     = threadIdx.x;

    const __half* Sb = d_Sh + (size_t)b * NVV * 64;

    // Load: thread t handles 4 halves (uint2) at (vl, o4). Coalesced.
#pragma unroll
    for (int p = 0; p < 4; p++) {
        int vl = p * 16 + (t >> 4);
        int o4 = (t & 15) * 4;
        int v  = vbase + vl;
        float2 f01 = make_float2(0.f, 0.f), f23 = make_float2(0.f, 0.f);
        if (v < NVV) {
            uint2 raw = *(const uint2*)(Sb + (size_t)v * 64 + o4);
            f01 = __half22float2(*(__half2*)&raw.x);
            f23 = __half22float2(*(__half2*)&raw.y);
        }
        s[vl][o4 + 0] = f01.x;
        s[vl][o4 + 1] = f01.y;
        s[vl][o4 + 2] = f23.x;
        s[vl][o4 + 3] = f23.y;
    }
    __syncthreads();

    const int o = t >> 2;
    const int q = t & 3;
    const int bg = b * 32 + (o >> 1);
    const float a = d_rstd[bg] * gamma[o];
    const float c = beta[o] - d_mean[bg] * a;
    size_t rowbase = (size_t)(b * 64 + o) * NVV;

#pragma unroll
    for (int u = 0; u < 8; u++) {
        int vl = q * 2 + u * 8;
        int v  = vbase + vl;
        if (v + 1 < NVV) {
            float2 w;
            w.x = fmaxf(fmaf(s[vl][o],     a, c), 0.f);
            w.y = fmaxf(fmaf(s[vl + 1][o], a, c), 0.f);
            *(float2*)(out + rowbase + v) = w;
        } else if (v < NVV) {
            out[rowbase + v] = fmaxf(fmaf(s[vl][o], a, c), 0.f);
        }
    }
}

// ---------------------------------------------------------------------------
extern "C" void kernel_launch(void* const* d_in, const int* in_sizes, int n_in,
                              void* d_out, int out_size)
{
    const float* x      = (const float*)d_in[0];
    const float* L_val  = (const float*)d_in[1];
    const float* EW_val = (const float*)d_in[2];
    const float* NS_val = (const float*)d_in[3];
    const float* coeffs = (const float*)d_in[4];
    const float* bias   = (const float*)d_in[5];
    const float* gamma  = (const float*)d_in[6];
    const float* beta   = (const float*)d_in[7];
    const int*   nbr    = (const int*)  d_in[8];
    float*       out    = (float*)d_out;

    static bool configured = false;
    if (!configured) {
        cudaFuncSetAttribute(k_stage1, cudaFuncAttributeMaxDynamicSharedMemorySize,
                             64 * (TM + 128) * (int)sizeof(float));
        configured = true;
    }

    // (0-3) Stage 1 in four launches — launch index 3 (profiled) is stage1
    {
        dim3 grid((NVP + TM - 1) / TM, 1, 4);           // (81, 1, 4) each
        size_t smem = 64 * (TM + 128) * sizeof(float);
        k_stage1<<<grid, 256, smem>>>(x, coeffs, 0,  0);
        k_stage1<<<grid, 256, smem>>>(x, coeffs, 0,  4);
        k_stage1<<<grid, 256, smem>>>(x, coeffs, 32, 0);
        k_stage1<<<grid, 256, smem>>>(x, coeffs, 32, 4);   // <-- ncu position
    }
    // (4) Stage 2: gather-combine -> d_Sh + partials
    {
        dim3 grid(VBLKS, 2);                            // (1281, 2)
        dim3 block(32, 4);
        k_stage2<<<grid, block>>>(L_val, EW_val, NS_val, nbr, bias);
    }
    // (5) Stage 2.5: group statistics
    k_reduce<<<256, 256>>>();
    // (6) Stage 3: transpose + normalize + ReLU
    {
        dim3 grid((NVV + 63) / 64, BB);                 // (641, 8)
        k_stage3<<<grid, 256>>>(out, gamma, beta);
    }
}

// round 16
// speedup vs baseline: 1.2725x; 1.2725x over previous
#include <cuda_runtime.h>
#include <cuda_fp16.h>
#include <cstddef>

#define NVV   40962
#define NVP   10242
#define BB    8
#define CC    64
#define KK    7
#define VBLKS 1281              // ceil(40962/32)
#define GN_N  (2*NVV)

// Scratch (device globals — zero-initialized; no allocations allowed)
__device__ float  d_Y0[(size_t)BB * NVP * 64];        // up-proj  [b][v][o], 21 MB
__device__ __half d_Yd[(size_t)BB * NVP * 64 * 4];    // {y1,y2,y3,0} [b][v][o][4], 42 MB
__device__ __half d_Sh[(size_t)BB * NVV * 64];        // pre-GN [b][v][o] fp16, 42 MB
__device__ float  d_psum[2 * VBLKS * 128];            // [half][vblk][(b&3)*32+g]
__device__ float  d_psq [2 * VBLKS * 128];
__device__ float  d_mean[256];
__device__ float  d_rstd[256];

#define FMA2(d, a, b, c) \
    asm("fma.rn.f32x2 %0, %1, %2, %3;" : "=l"(d) : "l"(a), "l"(b), "l"(c))

// ---------------------------------------------------------------------------
// Stage 1 (v2, occupancy-tuned): y_s[b,v,o] = sum_i coeffs[o,i,s] * x[b,i,v]
// Block tile: 16 o x 4 s x 128 v. Thread tile: 1 o x 4 s x 8 v (16 u64 acc).
// Static smem 48KB -> 4 blocks/SM. Single launch, grid (81, 4, 8).
// ---------------------------------------------------------------------------
__global__ void __launch_bounds__(256) k_stage1(const float* __restrict__ x,
                                                const float* __restrict__ coeffs)
{
    __shared__ float As[64 * 128];   // [i][vl]      32 KB
    __shared__ float Bs[64 * 64];    // [i][ol*4+s]  16 KB

    const int b     = blockIdx.z;
    const int obase = blockIdx.y * 16;
    const int vbase = blockIdx.x * 128;
    const int tid   = threadIdx.x;

    for (int t = tid; t < 64 * 64; t += 256) {
        int i  = t >> 6;
        int r  = t & 63;             // ol*4 + s
        Bs[t] = coeffs[((obase + (r >> 2)) * 64 + i) * 4 + (r & 3)];
    }
    for (int t = tid; t < 64 * 128; t += 256) {
        int i  = t >> 7;
        int vl = t & 127;
        int v  = vbase + vl;
        As[t]  = (v < NVP) ? x[(b * 64 + i) * NVP + v] : 0.f;
    }
    __syncthreads();

    const int ol    = tid & 15;          // o lane
    const int v_sub = (tid >> 4) * 8;    // 16 groups x 8 v

    unsigned long long acc[4][4];        // [s][v-pair]
#pragma unroll
    for (int s = 0; s < 4; s++)
#pragma unroll
        for (int c = 0; c < 4; c++) acc[s][c] = 0ULL;

#pragma unroll 4
    for (int i = 0; i < 64; i++) {
        const ulonglong2* Ap = (const ulonglong2*)(As + i * 128 + v_sub);
        ulonglong2 a01 = Ap[0];
        ulonglong2 a23 = Ap[1];
        unsigned long long av[4] = {a01.x, a01.y, a23.x, a23.y};
        float4 bv = *(const float4*)(Bs + i * 64 + ol * 4);
        float bsv[4] = {bv.x, bv.y, bv.z, bv.w};
#pragma unroll
        for (int s = 0; s < 4; s++) {
            unsigned bu = __float_as_uint(bsv[s]);
            unsigned long long bb;
            asm("mov.b64 %0, {%1, %1};" : "=l"(bb) : "r"(bu));
#pragma unroll
            for (int c = 0; c < 4; c++)
                FMA2(acc[s][c], av[c], bb, acc[s][c]);
        }
    }

    // Epilogue: per v, lane ol writes 1 float d_Y0 + 1 uint2 d_Yd.
    const int o = obase + ol;
#pragma unroll
    for (int c = 0; c < 4; c++) {
#pragma unroll
        for (int par = 0; par < 2; par++) {
            int v = vbase + v_sub + c * 2 + par;
            if (v < NVP) {
                float w[4];
#pragma unroll
                for (int s = 0; s < 4; s++) {
                    unsigned long long u = acc[s][c];
                    w[s] = __uint_as_float(par ? (unsigned)(u >> 32)
                                               : (unsigned)(u & 0xffffffffULL));
                }
                size_t vb = (size_t)b * NVP + v;
                d_Y0[vb * 64 + o] = w[0];
                __half2 p0 = __floats2half2_rn(w[1], w[2]);
                __half2 p1 = __floats2half2_rn(w[3], 0.f);
                uint2 pk;
                pk.x = *(unsigned*)&p0;
                pk.y = *(unsigned*)&p1;
                *(uint2*)(d_Yd + (vb * 64 + o) * 4) = pk;
            }
        }
    }
}

// ---------------------------------------------------------------------------
// Stage 2: gather-combine, 4 batches per block (ty = batch sub-index).
// tx = o-pair; one LDG.128 per hit serves both channels; half2 store to d_Sh.
// (unchanged from R15)
// ---------------------------------------------------------------------------
__global__ void __launch_bounds__(128) k_stage2(const float* __restrict__ Lw,
                                                const float* __restrict__ Ew,
                                                const float* __restrict__ Nw,
                                                const int*   __restrict__ nbr,
                                                const float* __restrict__ bias)
{
    __shared__ int   s_rj[32 * KK];
    __shared__ float s_rL[32 * KK], s_rE[32 * KK], s_rN[32 * KK];
    __shared__ int4  s_pk[32][KK];          // {j*32, wL, wE, wN}
    __shared__ int   s_cnt[32];

    const int vbase = blockIdx.x * 32;
    const int half  = blockIdx.y;           // batches [half*4, half*4+4)
    const int tx    = threadIdx.x;          // o-pair index (= GN group)
    const int ty    = threadIdx.y;          // batch sub-index
    const int tid   = ty * 32 + tx;
    const int b     = half * 4 + ty;

    for (int t = tid; t < 32 * KK; t += 128) {
        int gidx = vbase * KK + t;
        if (gidx < NVV * KK) {
            s_rj[t] = nbr[gidx];
            s_rL[t] = Lw[gidx]; s_rE[t] = Ew[gidx]; s_rN[t] = Nw[gidx];
        } else {
            s_rj[t] = NVP;
        }
    }
    __syncthreads();
    if (tid < 32) {
        int c = 0;
#pragma unroll
        for (int k = 0; k < KK; k++) {
            int j = s_rj[tid * KK + k];
            if (j < NVP) {
                s_pk[tid][c] = make_int4(j * 32,
                                         __float_as_int(s_rL[tid * KK + k]),
                                         __float_as_int(s_rE[tid * KK + k]),
                                         __float_as_int(s_rN[tid * KK + k]));
                c++;
            }
        }
        s_cnt[tid] = c;
    }
    __syncthreads();

    const float* Y0b  = d_Y0 + (size_t)b * NVP * 64;
    const uint4* Ydb4 = (const uint4*)d_Yd + (size_t)b * NVP * 32;
    __half*      Sb   = d_Sh + (size_t)b * NVV * 64;
    const float2 bo   = *(const float2*)(bias + tx * 2);
    float S = 0.f, Q = 0.f;

    int vmax = NVV - vbase; if (vmax > 32) vmax = 32;   // block-uniform
    for (int vl = 0; vl < vmax; vl++) {
        int v = vbase + vl;
        float acc0 = bo.x, acc1 = bo.y;
        if (v < NVP) {                            // warp-uniform
            float2 y0 = *(const float2*)(Y0b + v * 64 + tx * 2);
            acc0 += y0.x; acc1 += y0.y;
        }
        float aL0 = 0.f, aE0 = 0.f, aN0 = 0.f;
        float aL1 = 0.f, aE1 = 0.f, aN1 = 0.f;
        int cnt = s_cnt[vl];                      // warp-uniform
        for (int kk = 0; kk < cnt; kk++) {
            int4 pk = s_pk[vl][kk];               // LDS.128 (broadcast)
            uint4 q = Ydb4[(size_t)(pk.x + tx)];  // LDG.128: both channels
            float wL = __int_as_float(pk.y);
            float wE = __int_as_float(pk.z);
            float wN = __int_as_float(pk.w);
            float2 f01 = __half22float2(*(__half2*)&q.x);
            float  f3  = __low2float(*(__half2*)&q.y);
            float2 g01 = __half22float2(*(__half2*)&q.z);
            float  g3  = __low2float(*(__half2*)&q.w);
            aL0 = fmaf(wL, f01.x, aL0);
            aE0 = fmaf(wE, f01.y, aE0);
            aN0 = fmaf(wN, f3,    aN0);
            aL1 = fmaf(wL, g01.x, aL1);
            aE1 = fmaf(wE, g01.y, aE1);
            aN1 = fmaf(wN, g3,    aN1);
        }
        acc0 += aL0 + aE0 + aN0;
        acc1 += aL1 + aE1 + aN1;
        S += acc0 + acc1;
        Q = fmaf(acc0, acc0, Q);
        Q = fmaf(acc1, acc1, Q);
        *(__half2*)(Sb + (size_t)v * 64 + tx * 2) = __floats2half2_rn(acc0, acc1);
    }

    // Contiguous partial store: 512B per block
    size_t pidx = ((size_t)half * VBLKS + blockIdx.x) * 128 + tid;
    d_psum[pidx] = S;
    d_psq [pidx] = Q;
}

// ---------------------------------------------------------------------------
// Stage 2.5: reduce partials -> mean / rstd per (b, group). Fixed-order.
// ---------------------------------------------------------------------------
__global__ void __launch_bounds__(256) k_reduce()
{
    __shared__ float sS[256], sQ[256];
    const int bg   = blockIdx.x;
    const int tid  = threadIdx.x;
    const int bb   = bg >> 5;
    const int g    = bg & 31;
    const int half = bb >> 2;
    const int tloc = (bb & 3) * 32 + g;
    const float* P = d_psum + (size_t)half * VBLKS * 128 + tloc;
    const float* R = d_psq  + (size_t)half * VBLKS * 128 + tloc;
    float S = 0.f, Q = 0.f;
    for (int i = tid; i < VBLKS; i += 256) {
        S += P[(size_t)i * 128];
        Q += R[(size_t)i * 128];
    }
    sS[tid] = S; sQ[tid] = Q;
    __syncthreads();
    for (int st = 128; st > 0; st >>= 1) {
        if (tid < st) { sS[tid] += sS[tid + st]; sQ[tid] += sQ[tid + st]; }
        __syncthreads();
    }
    if (tid == 0) {
        float mean = sS[0] * (1.f / (float)GN_N);
        float var  = sQ[0] * (1.f / (float)GN_N) - mean * mean;
        d_mean[bg] = mean;
        d_rstd[bg] = rsqrtf(var + 1e-5f);
    }
}

// ---------------------------------------------------------------------------
// Stage 3: transpose fp16 [b][v][o] -> fp32 [b][o][v] + GN + ReLU.
// (unchanged from R15)
// ---------------------------------------------------------------------------
__global__ void __launch_bounds__(256) k_stage3(float* __restrict__ out,
                                                const float* __restrict__ gamma,
                                                const float* __restrict__ beta)
{
    __shared__ float s[64][65];

    const int b     = blockIdx.y;
    const int vbase = blockIdx.x * 64;
    const int t     = threadIdx.x;

    const __half* Sb = d_Sh + (size_t)b * NVV * 64;

#pragma unroll
    for (int p = 0; p < 4; p++) {
        int vl = p * 16 + (t >> 4);
        int o4 = (t & 15) * 4;
        int v  = vbase + vl;
        float2 f01 = make_float2(0.f, 0.f), f23 = make_float2(0.f, 0.f);
        if (v < NVV) {
            uint2 raw = *(const uint2*)(Sb + (size_t)v * 64 + o4);
            f01 = __half22float2(*(__half2*)&raw.x);
            f23 = __half22float2(*(__half2*)&raw.y);
        }
        s[vl][o4 + 0] = f01.x;
        s[vl][o4 + 1] = f01.y;
        s[vl][o4 + 2] = f23.x;
        s[vl][o4 + 3] = f23.y;
    }
    __syncthreads();

    const int o = t >> 2;
    const int q = t & 3;
    const int bg = b * 32 + (o >> 1);
    const float a = d_rstd[bg] * gamma[o];
    const float c = beta[o] - d_mean[bg] * a;
    size_t rowbase = (size_t)(b * 64 + o) * NVV;

#pragma unroll
    for (int u = 0; u < 8; u++) {
        int vl = q * 2 + u * 8;
        int v  = vbase + vl;
        if (v + 1 < NVV) {
            float2 w;
            w.x = fmaxf(fmaf(s[vl][o],     a, c), 0.f);
            w.y = fmaxf(fmaf(s[vl + 1][o], a, c), 0.f);
            *(float2*)(out + rowbase + v) = w;
        } else if (v < NVV) {
            out[rowbase + v] = fmaxf(fmaf(s[vl][o], a, c), 0.f);
        }
    }
}

// ---------------------------------------------------------------------------
extern "C" void kernel_launch(void* const* d_in, const int* in_sizes, int n_in,
                              void* d_out, int out_size)
{
    const float* x      = (const float*)d_in[0];
    const float* L_val  = (const float*)d_in[1];
    const float* EW_val = (const float*)d_in[2];
    const float* NS_val = (const float*)d_in[3];
    const float* coeffs = (const float*)d_in[4];
    const float* bias   = (const float*)d_in[5];
    const float* gamma  = (const float*)d_in[6];
    const float* beta   = (const float*)d_in[7];
    const int*   nbr    = (const int*)  d_in[8];
    float*       out    = (float*)d_out;

    // (0) Stage 1: projection GEMM, single launch
    {
        dim3 grid((NVP + 127) / 128, 4, BB);            // (81, 4, 8) = 2592
        k_stage1<<<grid, 256>>>(x, coeffs);
    }
    // (1) Stage 2: gather-combine -> d_Sh + partials
    {
        dim3 grid(VBLKS, 2);                            // (1281, 2)
        dim3 block(32, 4);
        k_stage2<<<grid, block>>>(L_val, EW_val, NS_val, nbr, bias);
    }
    // (2) Stage 2.5: group statistics
    k_reduce<<<256, 256>>>();
    // (3) Stage 3: transpose + normalize + ReLU          <-- ncu position
    {
        dim3 grid((NVV + 63) / 64, BB);                 // (641, 8)
        k_stage3<<<grid, 256>>>(out, gamma, beta);
    }
}